// round 7
// baseline (speedup 1.0000x reference)
#include <cuda_runtime.h>

#define T_    16384
#define NB    64
#define CIN   8
#define NH    32
#define NE    64
#define W_    48          // warm-up steps (state influence decays 2^-48 -> spike-exact)
#define LA_   256         // kA segment length
#define XSA   310         // kA staged cols (306 used + pad)
#define LB_   256         // kB segment length
#define MSZ   (8 * LB_ + W_ + 10)   // kB staged mask words per block

// Layer-1 spike bitmasks: word (b,t), bit = channel h. (allocation-free contract)
__device__ unsigned g_mask[(size_t)NB * T_];

// ---------------------------------------------------------------------------
// kA: conv1(k=3,same) + BN1 + LIF1 -> g_mask.  One warp per (b, 256-seg);
// lane = channel h.  x window staged once in smem (9.9KB).  4-phase register
// window; conv uses 6 parallel FMA chains (order-free: only spike decisions
// matter); LIF restructured exactly (tau=2 -> *0.5 exact).
// ---------------------------------------------------------------------------
__global__ void __launch_bounds__(32) kA(
    const float* __restrict__ x,  const float* __restrict__ w1,
    const float* __restrict__ b1, const float* __restrict__ g1,
    const float* __restrict__ be1,const float* __restrict__ m1,
    const float* __restrict__ v1)
{
    __shared__ float xs[XSA * CIN];
    const int lane = threadIdx.x;
    const int seg  = blockIdx.x;            // 0..63
    const int b    = blockIdx.y;
    const int t0   = seg * LA_;

    float wk0[8], wk1[8], wk2[8];
#pragma unroll
    for (int c = 0; c < 8; c++) {
        wk0[c] = __ldg(&w1[(lane * CIN + c) * 3 + 0]);
        wk1[c] = __ldg(&w1[(lane * CIN + c) * 3 + 1]);
        wk2[c] = __ldg(&w1[(lane * CIN + c) * 3 + 2]);
    }
    const float bias = __ldg(&b1[lane]);
    const float sc = __fmul_rn(__ldg(&g1[lane]), __frsqrt_rn(__fadd_rn(__ldg(&v1[lane]), 1e-5f)));
    const float sh = __fsub_rn(__ldg(&be1[lane]), __fmul_rn(__ldg(&m1[lane]), sc));

    const float* xb = x + (size_t)b * CIN * T_;
    const int tstart = (seg == 0) ? 0 : (t0 - W_);
    const int ncols  = ((seg == 0) ? LA_ : (LA_ + W_)) + 2;

    // Stage cols j -> time tstart-1+j, transposed (xs[j*8+c]); STS.128 pairs.
#pragma unroll 1
    for (int j = lane; j < ncols; j += 32) {
        int t = tstart - 1 + j;
        bool ok = ((unsigned)t < (unsigned)T_);
        float v0 = ok ? __ldg(xb + 0 * T_ + t) : 0.0f;
        float v1_ = ok ? __ldg(xb + 1 * T_ + t) : 0.0f;
        float v2_ = ok ? __ldg(xb + 2 * T_ + t) : 0.0f;
        float v3_ = ok ? __ldg(xb + 3 * T_ + t) : 0.0f;
        float v4_ = ok ? __ldg(xb + 4 * T_ + t) : 0.0f;
        float v5_ = ok ? __ldg(xb + 5 * T_ + t) : 0.0f;
        float v6_ = ok ? __ldg(xb + 6 * T_ + t) : 0.0f;
        float v7_ = ok ? __ldg(xb + 7 * T_ + t) : 0.0f;
        *(float4*)&xs[j * 8]     = make_float4(v0, v1_, v2_, v3_);
        *(float4*)&xs[j * 8 + 4] = make_float4(v4_, v5_, v6_, v7_);
    }
    __syncwarp();

    float vm = 0.0f;                 // pre-reset membrane of previous step
    bool  sp = false;                // spike at previous step
    unsigned mym = 0;

    const float* pt = xs;
    float4 Aa = *(const float4*)(pt + 0),  Ab = *(const float4*)(pt + 4);
    float4 Ba = *(const float4*)(pt + 8),  Bb = *(const float4*)(pt + 12);
    float4 Ca = *(const float4*)(pt + 16), Cb = *(const float4*)(pt + 20);
    float4 Da, Db;

#define KA_STEP(Pa,Pb,Qa,Qb,Ra,Rb,La,Lb,OFF,DOEMIT,SI) { \
    La = *(const float4*)(pt + (OFF)); \
    Lb = *(const float4*)(pt + (OFF) + 4); \
    float q0a = __fmul_rn(wk0[0], Pa.x), q0b = __fmul_rn(wk0[4], Pb.x); \
    float q1a = __fmul_rn(wk1[0], Qa.x), q1b = __fmul_rn(wk1[4], Qb.x); \
    float q2a = __fmul_rn(wk2[0], Ra.x), q2b = __fmul_rn(wk2[4], Rb.x); \
    q0a = __fmaf_rn(wk0[1], Pa.y, q0a);  q0b = __fmaf_rn(wk0[5], Pb.y, q0b); \
    q1a = __fmaf_rn(wk1[1], Qa.y, q1a);  q1b = __fmaf_rn(wk1[5], Qb.y, q1b); \
    q2a = __fmaf_rn(wk2[1], Ra.y, q2a);  q2b = __fmaf_rn(wk2[5], Rb.y, q2b); \
    q0a = __fmaf_rn(wk0[2], Pa.z, q0a);  q0b = __fmaf_rn(wk0[6], Pb.z, q0b); \
    q1a = __fmaf_rn(wk1[2], Qa.z, q1a);  q1b = __fmaf_rn(wk1[6], Qb.z, q1b); \
    q2a = __fmaf_rn(wk2[2], Ra.z, q2a);  q2b = __fmaf_rn(wk2[6], Rb.z, q2b); \
    q0a = __fmaf_rn(wk0[3], Pa.w, q0a);  q0b = __fmaf_rn(wk0[7], Pb.w, q0b); \
    q1a = __fmaf_rn(wk1[3], Qa.w, q1a);  q1b = __fmaf_rn(wk1[7], Qb.w, q1b); \
    q2a = __fmaf_rn(wk2[3], Ra.w, q2a);  q2b = __fmaf_rn(wk2[7], Rb.w, q2b); \
    float acc = __fadd_rn(__fadd_rn(__fadd_rn(q0a, q0b), __fadd_rn(q1a, q1b)), \
                          __fadd_rn(q2a, q2b)); \
    float u   = __fadd_rn(__fmul_rn(__fadd_rn(acc, bias), sc), sh); \
    float dns = __fsub_rn(u, vm); \
    float dd  = sp ? u    : dns; \
    float vp  = sp ? 0.0f : vm; \
    vm = __fmaf_rn(dd, 0.5f, vp); \
    sp = (vm >= 1.0f); \
    if (DOEMIT) { unsigned bal = __ballot_sync(0xffffffffu, sp); \
                  if (lane == (SI)) mym = bal; } }

    if (seg != 0) {
#pragma unroll 1
        for (int s = 0; s < W_; s += 4) {       // 12 warm rounds
            KA_STEP(Aa,Ab,Ba,Bb,Ca,Cb,Da,Db, 24, 0, 0)
            KA_STEP(Ba,Bb,Ca,Cb,Da,Db,Aa,Ab, 32, 0, 0)
            KA_STEP(Ca,Cb,Da,Db,Aa,Ab,Ba,Bb, 40, 0, 0)
            KA_STEP(Da,Db,Aa,Ab,Ba,Bb,Ca,Cb, 48, 0, 0)
            pt += 32;
        }
    }
    unsigned* mp = g_mask + (size_t)b * T_ + t0;
#pragma unroll 1
    for (int g = 0; g < 8; g++) {
#pragma unroll 1
        for (int si = 0; si < 32; si += 4) {
            KA_STEP(Aa,Ab,Ba,Bb,Ca,Cb,Da,Db, 24, 1, si + 0)
            KA_STEP(Ba,Bb,Ca,Cb,Da,Db,Aa,Ab, 32, 1, si + 1)
            KA_STEP(Ca,Cb,Da,Db,Aa,Ab,Ba,Bb, 40, 1, si + 2)
            KA_STEP(Da,Db,Aa,Ab,Ba,Bb,Ca,Cb, 48, 1, si + 3)
            pt += 32;
        }
        mp[g * 32 + lane] = mym;
    }
#undef KA_STEP
}

// ---------------------------------------------------------------------------
// kB: sparse conv2 + BN2 + LIF2 + output expansion -> out[B,E,T].
// Block = 8 warps = 8 consecutive 256-step segments of one batch.  Period-3
// register renaming replaces rolling-accumulator MOVs; single fused weight
// table (8-float stride) gives one address computation per set bit.  Lane
// covers e0=2*lane, e0+1; spikes accumulate as shifted bits; every 32 steps
// the warp's 64 channel-words expand via smem to coalesced float4 stores.
// ---------------------------------------------------------------------------
__global__ void __launch_bounds__(256) kB(
    const float* __restrict__ w2, const float* __restrict__ b2,
    const float* __restrict__ g2, const float* __restrict__ be2,
    const float* __restrict__ m2, const float* __restrict__ v2,
    float* __restrict__ out)
{
    __shared__ float    wsx[NH * 32 * 8];  // [c][lane][8]: k0e0,k0e1,k1e0,k1e1,k2e0,k2e1,pad,pad
    __shared__ unsigned ms[MSZ];
    __shared__ unsigned es[8][NE];         // per-warp expansion staging

    const int tid  = threadIdx.x;
    const int lane = tid & 31;
    const int w    = tid >> 5;
    const int b    = blockIdx.y;
    const int tblk = blockIdx.x * (8 * LB_);

    for (int i = tid; i < NH * 32; i += 256) {
        int c = i >> 5, l = i & 31, e0 = l * 2;
        float* wp = &wsx[i * 8];
        *(float4*)wp = make_float4(
            w2[(e0 * NH + c) * 3 + 0], w2[((e0 + 1) * NH + c) * 3 + 0],
            w2[(e0 * NH + c) * 3 + 1], w2[((e0 + 1) * NH + c) * 3 + 1]);
        *(float2*)(wp + 4) = make_float2(
            w2[(e0 * NH + c) * 3 + 2], w2[((e0 + 1) * NH + c) * 3 + 2]);
    }
    for (int j = tid; j < MSZ; j += 256) {
        int t = tblk - W_ - 1 + j;
        ms[j] = ((unsigned)t < (unsigned)T_) ? g_mask[(size_t)b * T_ + t] : 0u;
    }
    __syncthreads();

    const int segg = blockIdx.x * 8 + w;     // global 256-step segment id
    const int t0   = tblk + w * LB_;
    const int base = w * LB_;                // ms[base+j] <-> t = t0 - W_ - 1 + j
    const int e0   = lane * 2;

    const float sc0 = __fmul_rn(g2[e0],     __frsqrt_rn(__fadd_rn(v2[e0],     1e-5f)));
    const float sh0 = __fsub_rn(be2[e0],     __fmul_rn(m2[e0],     sc0));
    const float bb0 = b2[e0];
    const float sc1 = __fmul_rn(g2[e0 + 1], __frsqrt_rn(__fadd_rn(v2[e0 + 1], 1e-5f)));
    const float sh1 = __fsub_rn(be2[e0 + 1], __fmul_rn(m2[e0 + 1], sc1));
    const float bb1 = b2[e0 + 1];

    float aA0 = 0.f, aA1 = 0.f, aB0 = 0.f, aB1 = 0.f, aC0 = 0.f, aC1 = 0.f;
    float vm0 = 0.f, vm1 = 0.f;
    bool  sp0 = false, sp1 = false;
    unsigned me = 0, mo = 0;

    const int s0 = (segg == 0) ? W_ : 0;

    // Prime: word(t0-1) tap0 -> A; word(t0) tap1 -> A, tap0 -> B.
    { unsigned r = ms[base + s0];
      while (r) { int c = __ffs(r) - 1; r &= r - 1;
          float4 q = *(const float4*)&wsx[((c << 5) + lane) * 8];
          aA0 = __fadd_rn(aA0, q.x); aA1 = __fadd_rn(aA1, q.y); } }
    { unsigned r = ms[base + s0 + 1];
      while (r) { int c = __ffs(r) - 1; r &= r - 1;
          float4 q = *(const float4*)&wsx[((c << 5) + lane) * 8];
          aA0 = __fadd_rn(aA0, q.z); aA1 = __fadd_rn(aA1, q.w);
          aB0 = __fadd_rn(aB0, q.x); aB1 = __fadd_rn(aB1, q.y); } }

    // P = emit acc (gets tap2), Q gets tap1, R zeroed then gets tap0.
#define KB_STEPR(P0,P1,Q0,Q1,R0,R1,JW,DOEMIT,SI) { \
    R0 = 0.0f; R1 = 0.0f; \
    unsigned r = ms[JW]; \
    while (r) { int c = __ffs(r) - 1; r &= r - 1; \
        const float* wp = &wsx[((c << 5) + lane) * 8]; \
        float4 q = *(const float4*)wp; \
        float2 p = *(const float2*)(wp + 4); \
        P0 = __fadd_rn(P0, p.x); P1 = __fadd_rn(P1, p.y); \
        Q0 = __fadd_rn(Q0, q.z); Q1 = __fadd_rn(Q1, q.w); \
        R0 = __fadd_rn(R0, q.x); R1 = __fadd_rn(R1, q.y); } \
    float u0 = __fadd_rn(__fmul_rn(__fadd_rn(P0, bb0), sc0), sh0); \
    float u1 = __fadd_rn(__fmul_rn(__fadd_rn(P1, bb1), sc1), sh1); \
    float d0 = __fsub_rn(u0, vm0); float dd0 = sp0 ? u0 : d0; float vp0 = sp0 ? 0.0f : vm0; \
    vm0 = __fmaf_rn(dd0, 0.5f, vp0); sp0 = (vm0 >= 1.0f); \
    float d1 = __fsub_rn(u1, vm1); float dd1 = sp1 ? u1 : d1; float vp1 = sp1 ? 0.0f : vm1; \
    vm1 = __fmaf_rn(dd1, 0.5f, vp1); sp1 = (vm1 >= 1.0f); \
    if (DOEMIT) { me |= ((unsigned)sp0) << (SI); \
                  mo |= ((unsigned)sp1) << (SI); } }

#define KB_TRIPLE(JB, SI, DOEMIT) { \
    KB_STEPR(aA0,aA1,aB0,aB1,aC0,aC1, (JB),     DOEMIT, (SI))     \
    KB_STEPR(aB0,aB1,aC0,aC1,aA0,aA1, (JB) + 1, DOEMIT, (SI) + 1) \
    KB_STEPR(aC0,aC1,aA0,aA1,aB0,aB1, (JB) + 2, DOEMIT, (SI) + 2) }

    if (segg != 0) {
#pragma unroll 1
        for (int s = 0; s < W_; s += 3) {        // 16 triples = 48 steps
            KB_TRIPLE(base + s + 2, 0, 0)
        }
    }

    float* ob = out + (size_t)b * NE * T_ + t0;
#pragma unroll 1
    for (int g = 0; g < 8; g++) {
        const int jb = base + W_ + g * 32 + 2;
#pragma unroll 1
        for (int k = 0; k < 30; k += 3) {
            KB_TRIPLE(jb + k, k, 1)
        }
        KB_STEPR(aA0,aA1,aB0,aB1,aC0,aC1, jb + 30, 1, 30)
        KB_STEPR(aB0,aB1,aC0,aC1,aA0,aA1, jb + 31, 1, 31)
        // restore canonical roles: (A,B,C) <- (C,A,B)
        { float tx0 = aA0, tx1 = aA1;
          aA0 = aC0; aA1 = aC1;
          aC0 = aB0; aC1 = aB1;
          aB0 = tx0; aB1 = tx1; }

        *(uint2*)&es[w][e0] = make_uint2(me, mo);
        __syncwarp();
#pragma unroll
        for (int i = 0; i < 16; i++) {
            int idx = i * 32 + lane;          // 0..511
            int e   = idx >> 3;               // 0..63
            int q4  = (idx & 7) * 4;          // 0,4,..,28
            unsigned m = es[w][e];
            float4 v;
            v.x = ((m >> (q4 + 0)) & 1u) ? 1.0f : 0.0f;
            v.y = ((m >> (q4 + 1)) & 1u) ? 1.0f : 0.0f;
            v.z = ((m >> (q4 + 2)) & 1u) ? 1.0f : 0.0f;
            v.w = ((m >> (q4 + 3)) & 1u) ? 1.0f : 0.0f;
            *(float4*)&ob[(size_t)e * T_ + g * 32 + q4] = v;
        }
        __syncwarp();
        me = 0; mo = 0;
    }
#undef KB_TRIPLE
#undef KB_STEPR
}

// ---------------------------------------------------------------------------
extern "C" void kernel_launch(void* const* d_in, const int* in_sizes, int n_in,
                              void* d_out, int out_size)
{
    const float* x   = (const float*)d_in[0];
    const float* w1  = (const float*)d_in[1];
    const float* b1  = (const float*)d_in[2];
    const float* g1  = (const float*)d_in[3];
    const float* be1 = (const float*)d_in[4];
    const float* m1  = (const float*)d_in[5];
    const float* v1  = (const float*)d_in[6];
    const float* w2  = (const float*)d_in[7];
    const float* b2  = (const float*)d_in[8];
    const float* g2  = (const float*)d_in[9];
    const float* be2 = (const float*)d_in[10];
    const float* m2  = (const float*)d_in[11];
    const float* v2  = (const float*)d_in[12];
    float* out = (float*)d_out;

    kA<<<dim3(64, 64), 32>>>(x, w1, b1, g1, be1, m1, v1);
    kB<<<dim3(8, 64), 256>>>(w2, b2, g2, be2, m2, v2, out);
}

// round 8
// speedup vs baseline: 1.1891x; 1.1891x over previous
#include <cuda_runtime.h>

#define T_    16384
#define NB    64
#define CIN   8
#define NH    32
#define NE    64
#define W_    48          // warm-up steps (state influence decays 2^-48 -> spike-exact)
#define LA_   256         // kA segment length
#define XSA   312         // kA staged cols (306 used + pad)
#define LB_   256         // kB segment length
#define MSZ   (8 * LB_ + W_ + 10)   // kB staged mask words per block

typedef unsigned long long u64;

// Packed fp32 pair ops (Blackwell f32x2; IEEE rn per half -> bit-identical to scalar).
__device__ __forceinline__ u64 pk2(float lo, float hi) {
    u64 r; asm("mov.b64 %0,{%1,%2};" : "=l"(r) : "f"(lo), "f"(hi)); return r;
}
__device__ __forceinline__ void upk2(u64 v, float& lo, float& hi) {
    asm("mov.b64 {%0,%1},%2;" : "=f"(lo), "=f"(hi) : "l"(v));
}
__device__ __forceinline__ u64 fma2_(u64 a, u64 b, u64 c) {
    u64 d; asm("fma.rn.f32x2 %0,%1,%2,%3;" : "=l"(d) : "l"(a), "l"(b), "l"(c)); return d;
}
__device__ __forceinline__ u64 add2_(u64 a, u64 b) {
    u64 d; asm("add.rn.f32x2 %0,%1,%2;" : "=l"(d) : "l"(a), "l"(b)); return d;
}
__device__ __forceinline__ u64 mul2_(u64 a, u64 b) {
    u64 d; asm("mul.rn.f32x2 %0,%1,%2;" : "=l"(d) : "l"(a), "l"(b)); return d;
}

// Layer-1 spike bitmasks: word (b,t), bit = channel h. (allocation-free contract)
__device__ unsigned g_mask[(size_t)NB * T_];

// ---------------------------------------------------------------------------
// kA: conv1(k=3,same) + BN1 + LIF1 -> g_mask.  One warp per (b, 256-seg);
// lane = channel h.  x window staged in smem; 4-phase register window of
// packed pairs; conv = 12 FFMA2 (3 taps x 4 channel-pairs) + packed reduce.
// LIF restructured exactly (tau=2 -> *0.5 exact).
// ---------------------------------------------------------------------------
__global__ void __launch_bounds__(32) kA(
    const float* __restrict__ x,  const float* __restrict__ w1,
    const float* __restrict__ b1, const float* __restrict__ g1,
    const float* __restrict__ be1,const float* __restrict__ m1,
    const float* __restrict__ v1)
{
    __shared__ __align__(16) float xs[XSA * CIN];
    const int lane = threadIdx.x;
    const int seg  = blockIdx.x;            // 0..63
    const int b    = blockIdx.y;
    const int t0   = seg * LA_;

    // Packed weights: wp[k][j] = (w[2j], w[2j+1]) for tap k (input-channel pairs).
    u64 wp[3][4];
#pragma unroll
    for (int k = 0; k < 3; k++)
#pragma unroll
        for (int j = 0; j < 4; j++)
            wp[k][j] = pk2(__ldg(&w1[(lane * CIN + 2 * j) * 3 + k]),
                           __ldg(&w1[(lane * CIN + 2 * j + 1) * 3 + k]));
    const float bias = __ldg(&b1[lane]);
    const float sc = __fmul_rn(__ldg(&g1[lane]), __frsqrt_rn(__fadd_rn(__ldg(&v1[lane]), 1e-5f)));
    const float sh = __fsub_rn(__ldg(&be1[lane]), __fmul_rn(__ldg(&m1[lane]), sc));

    const float* xb = x + (size_t)b * CIN * T_;
    const int tstart = (seg == 0) ? 0 : (t0 - W_);
    const int ncols  = ((seg == 0) ? LA_ : (LA_ + W_)) + 2;

    // Stage cols j -> time tstart-1+j, transposed (xs[j*8+c]); STS.128 pairs.
#pragma unroll 1
    for (int j = lane; j < ncols; j += 32) {
        int t = tstart - 1 + j;
        bool ok = ((unsigned)t < (unsigned)T_);
        float v0 = ok ? __ldg(xb + 0 * T_ + t) : 0.0f;
        float v1_ = ok ? __ldg(xb + 1 * T_ + t) : 0.0f;
        float v2_ = ok ? __ldg(xb + 2 * T_ + t) : 0.0f;
        float v3_ = ok ? __ldg(xb + 3 * T_ + t) : 0.0f;
        float v4_ = ok ? __ldg(xb + 4 * T_ + t) : 0.0f;
        float v5_ = ok ? __ldg(xb + 5 * T_ + t) : 0.0f;
        float v6_ = ok ? __ldg(xb + 6 * T_ + t) : 0.0f;
        float v7_ = ok ? __ldg(xb + 7 * T_ + t) : 0.0f;
        *(float4*)&xs[j * 8]     = make_float4(v0, v1_, v2_, v3_);
        *(float4*)&xs[j * 8 + 4] = make_float4(v4_, v5_, v6_, v7_);
    }
    __syncwarp();

    float vm = 0.0f;                 // pre-reset membrane of previous step
    bool  sp = false;                // spike at previous step
    unsigned mym = 0;

    const float* pt = xs;
    // Window: Xa = pairs (c0,c1),(c2,c3); Xb = pairs (c4,c5),(c6,c7).
    ulonglong2 Aa = *(const ulonglong2*)(pt + 0),  Ab = *(const ulonglong2*)(pt + 4);
    ulonglong2 Ba = *(const ulonglong2*)(pt + 8),  Bb = *(const ulonglong2*)(pt + 12);
    ulonglong2 Ca = *(const ulonglong2*)(pt + 16), Cb = *(const ulonglong2*)(pt + 20);
    ulonglong2 Da, Db;

#define KA_STEP(Pa,Pb,Qa,Qb,Ra,Rb,La,Lb,OFF,DOEMIT,SI) { \
    La = *(const ulonglong2*)(pt + (OFF)); \
    Lb = *(const ulonglong2*)(pt + (OFF) + 4); \
    u64 c0 = mul2_(wp[0][0], Pa.x); \
    u64 c1 = mul2_(wp[1][0], Qa.x); \
    u64 c2 = mul2_(wp[2][0], Ra.x); \
    c0 = fma2_(wp[0][1], Pa.y, c0); \
    c1 = fma2_(wp[1][1], Qa.y, c1); \
    c2 = fma2_(wp[2][1], Ra.y, c2); \
    c0 = fma2_(wp[0][2], Pb.x, c0); \
    c1 = fma2_(wp[1][2], Qb.x, c1); \
    c2 = fma2_(wp[2][2], Rb.x, c2); \
    c0 = fma2_(wp[0][3], Pb.y, c0); \
    c1 = fma2_(wp[1][3], Qb.y, c1); \
    c2 = fma2_(wp[2][3], Rb.y, c2); \
    u64 s2 = add2_(c0, add2_(c1, c2)); \
    float s_lo, s_hi; upk2(s2, s_lo, s_hi); \
    float acc = __fadd_rn(s_lo, s_hi); \
    float u   = __fadd_rn(__fmul_rn(__fadd_rn(acc, bias), sc), sh); \
    float dns = __fsub_rn(u, vm); \
    float dd  = sp ? u    : dns; \
    float vp  = sp ? 0.0f : vm; \
    vm = __fmaf_rn(dd, 0.5f, vp); \
    sp = (vm >= 1.0f); \
    if (DOEMIT) { unsigned bal = __ballot_sync(0xffffffffu, sp); \
                  if (lane == (SI)) mym = bal; } }

    if (seg != 0) {
#pragma unroll 1
        for (int s = 0; s < W_; s += 4) {       // 12 warm rounds
            KA_STEP(Aa,Ab,Ba,Bb,Ca,Cb,Da,Db, 24, 0, 0)
            KA_STEP(Ba,Bb,Ca,Cb,Da,Db,Aa,Ab, 32, 0, 0)
            KA_STEP(Ca,Cb,Da,Db,Aa,Ab,Ba,Bb, 40, 0, 0)
            KA_STEP(Da,Db,Aa,Ab,Ba,Bb,Ca,Cb, 48, 0, 0)
            pt += 32;
        }
    }
    unsigned* mp = g_mask + (size_t)b * T_ + t0;
#pragma unroll 1
    for (int g = 0; g < 8; g++) {
#pragma unroll 1
        for (int si = 0; si < 32; si += 4) {
            KA_STEP(Aa,Ab,Ba,Bb,Ca,Cb,Da,Db, 24, 1, si + 0)
            KA_STEP(Ba,Bb,Ca,Cb,Da,Db,Aa,Ab, 32, 1, si + 1)
            KA_STEP(Ca,Cb,Da,Db,Aa,Ab,Ba,Bb, 40, 1, si + 2)
            KA_STEP(Da,Db,Aa,Ab,Ba,Bb,Ca,Cb, 48, 1, si + 3)
            pt += 32;
        }
        mp[g * 32 + lane] = mym;
    }
#undef KA_STEP
}

// ---------------------------------------------------------------------------
// kB: sparse conv2 + BN2 + LIF2 + output expansion -> out[B,E,T].
// Block = 8 warps = 8 consecutive 256-step segments of one batch.  SPLIT
// weight tables (float4 stride-16B + float2 stride-8B -> conflict-free LDS).
// Accumulators are packed f32x2 pairs (e0,e1): 3 FADD2 per set bit.  Period-3
// register renaming; spikes accumulate as shifted bits; every 32 steps the
// warp's 64 channel-words expand via smem to coalesced float4 stores.
// ---------------------------------------------------------------------------
__global__ void __launch_bounds__(256) kB(
    const float* __restrict__ w2, const float* __restrict__ b2,
    const float* __restrict__ g2, const float* __restrict__ be2,
    const float* __restrict__ m2, const float* __restrict__ v2,
    float* __restrict__ out)
{
    __shared__ __align__(16) float4 ws4[NH * 32];  // [c][lane] = {k0e0,k0e1,k1e0,k1e1}
    __shared__ __align__(8)  float2 ws2[NH * 32];  // [c][lane] = {k2e0,k2e1}
    __shared__ unsigned ms[MSZ];
    __shared__ unsigned es[8][NE];                 // per-warp expansion staging

    const int tid  = threadIdx.x;
    const int lane = tid & 31;
    const int w    = tid >> 5;
    const int b    = blockIdx.y;
    const int tblk = blockIdx.x * (8 * LB_);

    for (int i = tid; i < NH * 32; i += 256) {
        int c = i >> 5, l = i & 31, e0 = l * 2;
        ws4[i] = make_float4(w2[(e0 * NH + c) * 3 + 0], w2[((e0 + 1) * NH + c) * 3 + 0],
                             w2[(e0 * NH + c) * 3 + 1], w2[((e0 + 1) * NH + c) * 3 + 1]);
        ws2[i] = make_float2(w2[(e0 * NH + c) * 3 + 2], w2[((e0 + 1) * NH + c) * 3 + 2]);
    }
    for (int j = tid; j < MSZ; j += 256) {
        int t = tblk - W_ - 1 + j;
        ms[j] = ((unsigned)t < (unsigned)T_) ? g_mask[(size_t)b * T_ + t] : 0u;
    }
    __syncthreads();

    const int segg = blockIdx.x * 8 + w;     // global 256-step segment id
    const int t0   = tblk + w * LB_;
    const int base = w * LB_;                // ms[base+j] <-> t = t0 - W_ - 1 + j
    const int e0   = lane * 2;

    const float sc0 = __fmul_rn(g2[e0],     __frsqrt_rn(__fadd_rn(v2[e0],     1e-5f)));
    const float sh0 = __fsub_rn(be2[e0],     __fmul_rn(m2[e0],     sc0));
    const float sc1 = __fmul_rn(g2[e0 + 1], __frsqrt_rn(__fadd_rn(v2[e0 + 1], 1e-5f)));
    const float sh1 = __fsub_rn(be2[e0 + 1], __fmul_rn(m2[e0 + 1], sc1));
    const u64 bb2 = pk2(b2[e0], b2[e0 + 1]);
    const u64 sc2 = pk2(sc0, sc1);
    const u64 sh2 = pk2(sh0, sh1);

    u64 aA = 0ull, aB = 0ull, aC = 0ull;     // packed (e0,e1) accumulators
    float vm0 = 0.f, vm1 = 0.f;
    bool  sp0 = false, sp1 = false;
    unsigned me = 0, mo = 0;

    const int s0 = (segg == 0) ? W_ : 0;

    // Prime: word(t0-1) tap0 -> A; word(t0) tap1 -> A, tap0 -> B.
    { unsigned r = ms[base + s0];
      while (r) { int c = __ffs(r) - 1; r &= r - 1;
          ulonglong2 q = *(const ulonglong2*)&ws4[(c << 5) + lane];
          aA = add2_(aA, q.x); } }
    { unsigned r = ms[base + s0 + 1];
      while (r) { int c = __ffs(r) - 1; r &= r - 1;
          ulonglong2 q = *(const ulonglong2*)&ws4[(c << 5) + lane];
          aA = add2_(aA, q.y);
          aB = add2_(aB, q.x); } }

    // P = emit acc (gets tap2), Q gets tap1, R zeroed then gets tap0.
#define KB_STEPR(P_,Q_,R_,JW,DOEMIT,SI) { \
    R_ = 0ull; \
    unsigned r = ms[JW]; \
    while (r) { int c = __ffs(r) - 1; r &= r - 1; \
        ulonglong2 q = *(const ulonglong2*)&ws4[(c << 5) + lane]; \
        u64 p = *(const u64*)&ws2[(c << 5) + lane]; \
        P_ = add2_(P_, p); \
        Q_ = add2_(Q_, q.y); \
        R_ = add2_(R_, q.x); } \
    u64 u2 = fma2_(add2_(P_, bb2), sc2, sh2); \
    float u0, u1; upk2(u2, u0, u1); \
    float d0 = __fsub_rn(u0, vm0); float dd0 = sp0 ? u0 : d0; float vp0 = sp0 ? 0.0f : vm0; \
    vm0 = __fmaf_rn(dd0, 0.5f, vp0); sp0 = (vm0 >= 1.0f); \
    float d1 = __fsub_rn(u1, vm1); float dd1 = sp1 ? u1 : d1; float vp1 = sp1 ? 0.0f : vm1; \
    vm1 = __fmaf_rn(dd1, 0.5f, vp1); sp1 = (vm1 >= 1.0f); \
    if (DOEMIT) { me |= ((unsigned)sp0) << (SI); \
                  mo |= ((unsigned)sp1) << (SI); } }

#define KB_TRIPLE(JB, SI, DOEMIT) { \
    KB_STEPR(aA, aB, aC, (JB),     DOEMIT, (SI))     \
    KB_STEPR(aB, aC, aA, (JB) + 1, DOEMIT, (SI) + 1) \
    KB_STEPR(aC, aA, aB, (JB) + 2, DOEMIT, (SI) + 2) }

    if (segg != 0) {
#pragma unroll 1
        for (int s = 0; s < W_; s += 3) {        // 16 triples = 48 steps
            KB_TRIPLE(base + s + 2, 0, 0)
        }
    }

    float* ob = out + (size_t)b * NE * T_ + t0;
#pragma unroll 1
    for (int g = 0; g < 8; g++) {
        const int jb = base + W_ + g * 32 + 2;
#pragma unroll 1
        for (int k = 0; k < 30; k += 3) {
            KB_TRIPLE(jb + k, k, 1)
        }
        KB_STEPR(aA, aB, aC, jb + 30, 1, 30)
        KB_STEPR(aB, aC, aA, jb + 31, 1, 31)
        // restore canonical roles: (A,B,C) <- (C,A,B)
        { u64 tx = aA; aA = aC; aC = aB; aB = tx; }

        *(uint2*)&es[w][e0] = make_uint2(me, mo);
        __syncwarp();
#pragma unroll
        for (int i = 0; i < 16; i++) {
            int idx = i * 32 + lane;          // 0..511
            int e   = idx >> 3;               // 0..63
            int q4  = (idx & 7) * 4;          // 0,4,..,28
            unsigned m = es[w][e];
            float4 v;
            v.x = ((m >> (q4 + 0)) & 1u) ? 1.0f : 0.0f;
            v.y = ((m >> (q4 + 1)) & 1u) ? 1.0f : 0.0f;
            v.z = ((m >> (q4 + 2)) & 1u) ? 1.0f : 0.0f;
            v.w = ((m >> (q4 + 3)) & 1u) ? 1.0f : 0.0f;
            *(float4*)&ob[(size_t)e * T_ + g * 32 + q4] = v;
        }
        __syncwarp();
        me = 0; mo = 0;
    }
#undef KB_TRIPLE
#undef KB_STEPR
}

// ---------------------------------------------------------------------------
extern "C" void kernel_launch(void* const* d_in, const int* in_sizes, int n_in,
                              void* d_out, int out_size)
{
    const float* x   = (const float*)d_in[0];
    const float* w1  = (const float*)d_in[1];
    const float* b1  = (const float*)d_in[2];
    const float* g1  = (const float*)d_in[3];
    const float* be1 = (const float*)d_in[4];
    const float* m1  = (const float*)d_in[5];
    const float* v1  = (const float*)d_in[6];
    const float* w2  = (const float*)d_in[7];
    const float* b2  = (const float*)d_in[8];
    const float* g2  = (const float*)d_in[9];
    const float* be2 = (const float*)d_in[10];
    const float* m2  = (const float*)d_in[11];
    const float* v2  = (const float*)d_in[12];
    float* out = (float*)d_out;

    kA<<<dim3(64, 64), 32>>>(x, w1, b1, g1, be1, m1, v1);
    kB<<<dim3(8, 64), 256>>>(w2, b2, g2, be2, m2, v2, out);
}

// round 9
// speedup vs baseline: 1.2972x; 1.0909x over previous
#include <cuda_runtime.h>

#define T_    16384
#define NB    64
#define CIN   8
#define NH    32
#define NE    64
#define W_    48          // warm-up steps (state influence decays 2^-48 -> spike-exact)
#define LA_   256         // kA segment length
#define XSB   168         // kA phase buffer cols (max 162 staged + dangling + pad)
#define LB_   256         // kB segment length
#define MSZ   2112        // kB staged mask words per block (max index 2099)

typedef unsigned long long u64;

// Packed fp32 pair ops (f32x2; IEEE rn per half -> bit-identical to scalar).
__device__ __forceinline__ u64 pk2(float lo, float hi) {
    u64 r; asm("mov.b64 %0,{%1,%2};" : "=l"(r) : "f"(lo), "f"(hi)); return r;
}
__device__ __forceinline__ void upk2(u64 v, float& lo, float& hi) {
    asm("mov.b64 {%0,%1},%2;" : "=f"(lo), "=f"(hi) : "l"(v));
}
__device__ __forceinline__ u64 fma2_(u64 a, u64 b, u64 c) {
    u64 d; asm("fma.rn.f32x2 %0,%1,%2,%3;" : "=l"(d) : "l"(a), "l"(b), "l"(c)); return d;
}
__device__ __forceinline__ u64 add2_(u64 a, u64 b) {
    u64 d; asm("add.rn.f32x2 %0,%1,%2;" : "=l"(d) : "l"(a), "l"(b)); return d;
}
__device__ __forceinline__ u64 mul2_(u64 a, u64 b) {
    u64 d; asm("mul.rn.f32x2 %0,%1,%2;" : "=l"(d) : "l"(a), "l"(b)); return d;
}

// Layer-1 spike bitmasks: word (b,t), bit = channel h. (allocation-free contract)
__device__ unsigned g_mask[(size_t)NB * T_];

// ---------------------------------------------------------------------------
// kA: conv1(k=3,same) + BN1 + LIF1 -> g_mask.  One warp per (b, 256-seg);
// lane = channel h.  x window staged in smem in TWO phases (5.3KB buffer ->
// all 4096 warps resident, single wave).  Packed-pair conv (12 FFMA2-class
// ops); BN folded to one FMA (conv bias is zero -> exact); 4-op LIF on
// post-reset state (tau=2 -> *0.5 exact).
// ---------------------------------------------------------------------------
__global__ void __launch_bounds__(32) kA(
    const float* __restrict__ x,  const float* __restrict__ w1,
    const float* __restrict__ b1, const float* __restrict__ g1,
    const float* __restrict__ be1,const float* __restrict__ m1,
    const float* __restrict__ v1)
{
    __shared__ __align__(16) float xs[XSB * CIN];
    const int lane = threadIdx.x;
    const int seg  = blockIdx.x;            // 0..63
    const int b    = blockIdx.y;
    const int t0   = seg * LA_;

    // Packed weights: wp[k][j] = (w[2j], w[2j+1]) for tap k.
    u64 wp[3][4];
#pragma unroll
    for (int k = 0; k < 3; k++)
#pragma unroll
        for (int j = 0; j < 4; j++)
            wp[k][j] = pk2(__ldg(&w1[(lane * CIN + 2 * j) * 3 + k]),
                           __ldg(&w1[(lane * CIN + 2 * j + 1) * 3 + k]));
    const float bias = __ldg(&b1[lane]);    // zero in dataset; fold exactly
    const float sc = __fmul_rn(__ldg(&g1[lane]), __frsqrt_rn(__fadd_rn(__ldg(&v1[lane]), 1e-5f)));
    const float sh0 = __fsub_rn(__ldg(&be1[lane]), __fmul_rn(__ldg(&m1[lane]), sc));
    const float sh  = __fmaf_rn(bias, sc, sh0);  // (acc+bias)*sc+sh == fma(acc,sc,sh') for bias=0

    const float* xb = x + (size_t)b * CIN * T_;
    float vr = 0.0f;                 // post-reset membrane
    unsigned mym = 0;
    unsigned* mp = g_mask + (size_t)b * T_ + t0;
    int grp = 0;

#define KA_STEP(Pa,Pb,Qa,Qb,Ra,Rb,La,Lb,OFF,DOEMIT,SI) { \
    La = *(const ulonglong2*)(pt + (OFF)); \
    Lb = *(const ulonglong2*)(pt + (OFF) + 4); \
    u64 c0 = mul2_(wp[0][0], Pa.x); \
    u64 c1 = mul2_(wp[1][0], Qa.x); \
    u64 c2 = mul2_(wp[2][0], Ra.x); \
    c0 = fma2_(wp[0][1], Pa.y, c0); \
    c1 = fma2_(wp[1][1], Qa.y, c1); \
    c2 = fma2_(wp[2][1], Ra.y, c2); \
    c0 = fma2_(wp[0][2], Pb.x, c0); \
    c1 = fma2_(wp[1][2], Qb.x, c1); \
    c2 = fma2_(wp[2][2], Rb.x, c2); \
    c0 = fma2_(wp[0][3], Pb.y, c0); \
    c1 = fma2_(wp[1][3], Qb.y, c1); \
    c2 = fma2_(wp[2][3], Rb.y, c2); \
    u64 s2 = add2_(c0, add2_(c1, c2)); \
    float s_lo, s_hi; upk2(s2, s_lo, s_hi); \
    float acc = __fadd_rn(s_lo, s_hi); \
    float u   = __fmaf_rn(acc, sc, sh); \
    float vp  = __fmaf_rn(__fsub_rn(u, vr), 0.5f, vr); \
    bool  spk = (vp >= 1.0f); \
    vr = spk ? 0.0f : vp; \
    if (DOEMIT) { unsigned bal = __ballot_sync(0xffffffffu, spk); \
                  if (lane == (SI)) mym = bal; } }

#define KA_QUAD(DOEMIT, SB) { \
    KA_STEP(Aa,Ab,Ba,Bb,Ca,Cb,Da,Db, 24, DOEMIT, (SB) + 0) \
    KA_STEP(Ba,Bb,Ca,Cb,Da,Db,Aa,Ab, 32, DOEMIT, (SB) + 1) \
    KA_STEP(Ca,Cb,Da,Db,Aa,Ab,Ba,Bb, 40, DOEMIT, (SB) + 2) \
    KA_STEP(Da,Db,Aa,Ab,Ba,Bb,Ca,Cb, 48, DOEMIT, (SB) + 3) \
    pt += 32; }

#pragma unroll 1
    for (int ph = 0; ph < 2; ph++) {
        // Phase 0: cols j <-> t = t0-49+j, 146 cols (48 warm + 96 emit).
        // Phase 1: cols j <-> t = t0+95+j, 162 cols (160 emit).
        const int tbase = (ph == 0) ? (t0 - 49) : (t0 + 95);
        const int ncols = (ph == 0) ? 146 : 162;
        __syncwarp();
#pragma unroll 1
        for (int j = lane; j < ncols; j += 32) {
            int t = tbase + j;
            bool ok = ((unsigned)t < (unsigned)T_);
            float v0 = ok ? __ldg(xb + 0 * T_ + t) : 0.0f;
            float v1_ = ok ? __ldg(xb + 1 * T_ + t) : 0.0f;
            float v2_ = ok ? __ldg(xb + 2 * T_ + t) : 0.0f;
            float v3_ = ok ? __ldg(xb + 3 * T_ + t) : 0.0f;
            float v4_ = ok ? __ldg(xb + 4 * T_ + t) : 0.0f;
            float v5_ = ok ? __ldg(xb + 5 * T_ + t) : 0.0f;
            float v6_ = ok ? __ldg(xb + 6 * T_ + t) : 0.0f;
            float v7_ = ok ? __ldg(xb + 7 * T_ + t) : 0.0f;
            *(float4*)&xs[j * 8]     = make_float4(v0, v1_, v2_, v3_);
            *(float4*)&xs[j * 8 + 4] = make_float4(v4_, v5_, v6_, v7_);
        }
        __syncwarp();

        // Prime window. Phase 0 seg==0 skips warm-up: start at col 48 (t=-1).
        const float* pt = xs + ((ph == 0 && seg == 0) ? 48 * 8 : 0);
        ulonglong2 Aa = *(const ulonglong2*)(pt + 0),  Ab = *(const ulonglong2*)(pt + 4);
        ulonglong2 Ba = *(const ulonglong2*)(pt + 8),  Bb = *(const ulonglong2*)(pt + 12);
        ulonglong2 Ca = *(const ulonglong2*)(pt + 16), Cb = *(const ulonglong2*)(pt + 20);
        ulonglong2 Da, Db;

        if (ph == 0 && seg != 0) {
#pragma unroll 1
            for (int q = 0; q < 12; q++) KA_QUAD(0, 0)      // 48 warm steps
        }
        const int ng = (ph == 0) ? 3 : 5;                    // emit groups this phase
#pragma unroll 1
        for (int g = 0; g < ng; g++) {
#pragma unroll 1
            for (int q = 0; q < 8; q++) KA_QUAD(1, q * 4)    // 32 emit steps
            mp[grp * 32 + lane] = mym;
            grp++;
        }
    }
#undef KA_QUAD
#undef KA_STEP
}

// ---------------------------------------------------------------------------
// kB: sparse conv2 + BN2 + LIF2 + output expansion -> out[B,E,T].
// Block = 8 warps = 8 consecutive 256-step segments of one batch.  Masks
// staged with -51 offset so warm/emit quads read aligned uint4 (one LDS.128
// per 4 steps).  Period-4 accumulator renaming (no fixup MOVs).  Split
// conflict-free weight tables; packed (e0,e1) accumulators: 3 FADD2/bit.
// 4-op LIF per channel; spikes accumulate as shifted bits; every 32 steps
// the warp's 64 channel-words expand via smem to coalesced float4 stores.
// ---------------------------------------------------------------------------
__global__ void __launch_bounds__(256) kB(
    const float* __restrict__ w2, const float* __restrict__ b2,
    const float* __restrict__ g2, const float* __restrict__ be2,
    const float* __restrict__ m2, const float* __restrict__ v2,
    float* __restrict__ out)
{
    __shared__ __align__(16) float4 ws4[NH * 32];  // [c][lane] = {k0e0,k0e1,k1e0,k1e1}
    __shared__ __align__(8)  float2 ws2[NH * 32];  // [c][lane] = {k2e0,k2e1}
    __shared__ __align__(16) unsigned ms[MSZ];
    __shared__ unsigned es[8][NE];                 // per-warp expansion staging

    const int tid  = threadIdx.x;
    const int lane = tid & 31;
    const int w    = tid >> 5;
    const int b    = blockIdx.y;
    const int tblk = blockIdx.x * (8 * LB_);

    for (int i = tid; i < NH * 32; i += 256) {
        int c = i >> 5, l = i & 31, e0 = l * 2;
        ws4[i] = make_float4(w2[(e0 * NH + c) * 3 + 0], w2[((e0 + 1) * NH + c) * 3 + 0],
                             w2[(e0 * NH + c) * 3 + 1], w2[((e0 + 1) * NH + c) * 3 + 1]);
        ws2[i] = make_float2(w2[(e0 * NH + c) * 3 + 2], w2[((e0 + 1) * NH + c) * 3 + 2]);
    }
    for (int j = tid; j < MSZ; j += 256) {
        int t = tblk + j - 51;                     // ms[j] <-> mask word at time t
        ms[j] = ((unsigned)t < (unsigned)T_) ? g_mask[(size_t)b * T_ + t] : 0u;
    }
    __syncthreads();

    const int segg = blockIdx.x * 8 + w;     // global 256-step segment id
    const int t0   = tblk + w * LB_;
    const unsigned* msw = ms + w * LB_;      // msw[j] <-> time t0 + j - 51
    const int e0   = lane * 2;

    const float sc0 = __fmul_rn(g2[e0],     __frsqrt_rn(__fadd_rn(v2[e0],     1e-5f)));
    const float sh0 = __fsub_rn(be2[e0],     __fmul_rn(m2[e0],     sc0));
    const float sc1 = __fmul_rn(g2[e0 + 1], __frsqrt_rn(__fadd_rn(v2[e0 + 1], 1e-5f)));
    const float sh1 = __fsub_rn(be2[e0 + 1], __fmul_rn(m2[e0 + 1], sc1));
    // conv bias is zero in dataset -> fold exactly: u = fma(acc, sc, bb*sc+sh)
    const u64 sc2 = pk2(sc0, sc1);
    const u64 sh2 = pk2(__fmaf_rn(b2[e0], sc0, sh0), __fmaf_rn(b2[e0 + 1], sc1, sh1));

    u64 aA = 0ull, aB = 0ull, aC = 0ull, aD = 0ull;   // packed (e0,e1) accumulators
    float vr0 = 0.f, vr1 = 0.f;                        // post-reset membranes
    unsigned me = 0, mo = 0;

    // Prime.  Word m[ts-1] -> tap0 to first emit acc; word m[ts] -> tap1 + tap0.
    const int pj = (segg == 0) ? 50 : 2;     // seg0: words t0-1,t0 ; else t0-49,t0-48
    { unsigned r = msw[pj];
      while (r) { int c = __ffs(r) - 1; r &= r - 1;
          ulonglong2 q = *(const ulonglong2*)&ws4[(c << 5) + lane];
          aA = add2_(aA, q.x); } }
    { unsigned r = msw[pj + 1];
      while (r) { int c = __ffs(r) - 1; r &= r - 1;
          ulonglong2 q = *(const ulonglong2*)&ws4[(c << 5) + lane];
          aA = add2_(aA, q.y);
          aB = add2_(aB, q.x); } }

    // One LIF step: P = finished acc (gets tap2), Q gets tap1, R fresh (tap0).
#define KB_ST(P_,Q_,R_, RM, DOEMIT, SI) { \
    R_ = 0ull; \
    unsigned r = (RM); \
    while (r) { int c = __ffs(r) - 1; r &= r - 1; \
        ulonglong2 q = *(const ulonglong2*)&ws4[(c << 5) + lane]; \
        u64 p = *(const u64*)&ws2[(c << 5) + lane]; \
        P_ = add2_(P_, p); \
        Q_ = add2_(Q_, q.y); \
        R_ = add2_(R_, q.x); } \
    u64 u2 = fma2_(P_, sc2, sh2); \
    float u0, u1; upk2(u2, u0, u1); \
    float vp0 = __fmaf_rn(__fsub_rn(u0, vr0), 0.5f, vr0); \
    bool  s0_ = (vp0 >= 1.0f);  vr0 = s0_ ? 0.0f : vp0; \
    float vp1 = __fmaf_rn(__fsub_rn(u1, vr1), 0.5f, vr1); \
    bool  s1_ = (vp1 >= 1.0f);  vr1 = s1_ ? 0.0f : vp1; \
    if (DOEMIT) { me |= ((unsigned)s0_) << (SI); \
                  mo |= ((unsigned)s1_) << (SI); } }

#define KB_QUAD(JQ, DOEMIT, SB) { \
    uint4 m4 = *(const uint4*)&msw[JQ]; \
    KB_ST(aA, aB, aC, m4.x, DOEMIT, (SB) + 0) \
    KB_ST(aB, aC, aD, m4.y, DOEMIT, (SB) + 1) \
    KB_ST(aC, aD, aA, m4.z, DOEMIT, (SB) + 2) \
    KB_ST(aD, aA, aB, m4.w, DOEMIT, (SB) + 3) }

    if (segg != 0) {
#pragma unroll 1
        for (int q = 0; q < 12; q++) KB_QUAD(4 + q * 4, 0, 0)     // 48 warm steps
    }

    float* ob = out + (size_t)b * NE * T_ + t0;
#pragma unroll 1
    for (int g = 0; g < 8; g++) {
        const int jb = 52 + g * 32;
#pragma unroll 1
        for (int q = 0; q < 8; q++) KB_QUAD(jb + q * 4, 1, q * 4)  // 32 emit steps

        *(uint2*)&es[w][e0] = make_uint2(me, mo);
        __syncwarp();
#pragma unroll
        for (int i = 0; i < 16; i++) {
            int idx = i * 32 + lane;          // 0..511
            int e   = idx >> 3;               // 0..63
            int q4  = (idx & 7) * 4;          // 0,4,..,28
            unsigned m = es[w][e];
            float4 v;
            v.x = ((m >> (q4 + 0)) & 1u) ? 1.0f : 0.0f;
            v.y = ((m >> (q4 + 1)) & 1u) ? 1.0f : 0.0f;
            v.z = ((m >> (q4 + 2)) & 1u) ? 1.0f : 0.0f;
            v.w = ((m >> (q4 + 3)) & 1u) ? 1.0f : 0.0f;
            *(float4*)&ob[(size_t)e * T_ + g * 32 + q4] = v;
        }
        __syncwarp();
        me = 0; mo = 0;
    }
#undef KB_QUAD
#undef KB_ST
}

// ---------------------------------------------------------------------------
extern "C" void kernel_launch(void* const* d_in, const int* in_sizes, int n_in,
                              void* d_out, int out_size)
{
    const float* x   = (const float*)d_in[0];
    const float* w1  = (const float*)d_in[1];
    const float* b1  = (const float*)d_in[2];
    const float* g1  = (const float*)d_in[3];
    const float* be1 = (const float*)d_in[4];
    const float* m1  = (const float*)d_in[5];
    const float* v1  = (const float*)d_in[6];
    const float* w2  = (const float*)d_in[7];
    const float* b2  = (const float*)d_in[8];
    const float* g2  = (const float*)d_in[9];
    const float* be2 = (const float*)d_in[10];
    const float* m2  = (const float*)d_in[11];
    const float* v2  = (const float*)d_in[12];
    float* out = (float*)d_out;

    kA<<<dim3(64, 64), 32>>>(x, w1, b1, g1, be1, m1, v1);
    kB<<<dim3(8, 64), 256>>>(w2, b2, g2, be2, m2, v2, out);
}